// round 9
// baseline (speedup 1.0000x reference)
#include <cuda_runtime.h>
#include <cuda_bf16.h>

#define BETA   0.001f
#define TPB    256
#define WPB    8        // warps per block, one segment per warp
#define MAXB   1024
#define LOG2E  1.4426950408889634f
#define LN2    0.6931471805599453f

typedef unsigned long long u64;

__device__ float    g_part[MAXB];
__device__ unsigned g_done = 0;

__device__ __forceinline__ float ex2f(float x){ float r; asm("ex2.approx.f32 %0,%1;":"=f"(r):"f"(x)); return r; }
__device__ __forceinline__ float lg2f(float x){ float r; asm("lg2.approx.f32 %0,%1;":"=f"(r):"f"(x)); return r; }

__device__ __forceinline__ u64 pack2(float x, float y){ u64 r; asm("mov.b64 %0,{%1,%2};":"=l"(r):"f"(x),"f"(y)); return r; }
__device__ __forceinline__ void unpack2(u64 v, float& x, float& y){ asm("mov.b64 {%0,%1},%2;":"=f"(x),"=f"(y):"l"(v)); }
__device__ __forceinline__ u64 fma2(u64 a, u64 b, u64 c){ u64 r; asm("fma.rn.f32x2 %0,%1,%2,%3;":"=l"(r):"l"(a),"l"(b),"l"(c)); return r; }
__device__ __forceinline__ u64 mul2(u64 a, u64 b){ u64 r; asm("mul.rn.f32x2 %0,%1,%2;":"=l"(r):"l"(a),"l"(b)); return r; }

// i-chunk at b[0..31] (shared, zero-padded) against NJ j-chunk chains.
// Chain j accumulates prod(1 + e[j]*b_i) in packed f32x2 (lo: even i, hi: odd i);
// lg2 taken every 16 factors (8 per packed lane). Factor <= ~2^14.1 (|x|<=4.8),
// 8 per lane -> product <= 2^113 < FLT_MAX. e==0 (invalid j) -> contributes 0.
// Chain 0 is the DIAGONAL chunk (rj==ri): its sum goes to accd (weight 1/2 later).
template<int NJ>
__device__ __forceinline__ void sweepN(const float* __restrict__ b,
                                       const float* __restrict__ e,
                                       float& acc, float& accd)
{
    u64 E[NJ];
    #pragma unroll
    for (int j = 0; j < NJ; ++j) E[j] = pack2(e[j], e[j]);
    const u64 one = pack2(1.0f, 1.0f);

    float r[NJ];
    #pragma unroll
    for (int j = 0; j < NJ; ++j) r[j] = 0.0f;

    #pragma unroll
    for (int blk = 0; blk < 2; ++blk) {     // 16 elements (8 packed factors) per blk
        const float* bb = b + blk * 16;
        float4 v0 = *(const float4*)(bb);
        float4 v1 = *(const float4*)(bb + 4);
        float4 v2 = *(const float4*)(bb + 8);
        float4 v3 = *(const float4*)(bb + 12);
        u64 B0 = pack2(v0.x, v0.y);
        u64 B1 = pack2(v0.z, v0.w);
        u64 B2 = pack2(v1.x, v1.y);
        u64 B3 = pack2(v1.z, v1.w);
        u64 B4 = pack2(v2.x, v2.y);
        u64 B5 = pack2(v2.z, v2.w);
        u64 B6 = pack2(v3.x, v3.y);
        u64 B7 = pack2(v3.z, v3.w);
        #pragma unroll
        for (int j = 0; j < NJ; ++j) {
            u64 P = mul2(E[j], B0);
            P = fma2(one, P, one);          // P = 1 + t0
            u64 t;
            t = mul2(E[j], B1); P = fma2(P, t, P);
            t = mul2(E[j], B2); P = fma2(P, t, P);
            t = mul2(E[j], B3); P = fma2(P, t, P);
            t = mul2(E[j], B4); P = fma2(P, t, P);
            t = mul2(E[j], B5); P = fma2(P, t, P);
            t = mul2(E[j], B6); P = fma2(P, t, P);
            t = mul2(E[j], B7); P = fma2(P, t, P);
            float pa, pb; unpack2(P, pa, pb);
            r[j] += lg2f(pa * pb);
        }
    }
    accd += r[0];
    #pragma unroll
    for (int j = 1; j < NJ; ++j) acc += r[j];
}

__global__ void __launch_bounds__(TPB) rm_kernel(
    const float* __restrict__ logits,
    const void*  __restrict__ cu_raw,
    int n_seg,
    float* __restrict__ out)
{
    __shared__ __align__(16) float em[WPB][128];   // e^{-x}, zero-padded
    __shared__ float part[WPB];
    __shared__ float ws[TPB / 32];
    __shared__ bool  isLast;

    const int tid  = threadIdx.x;
    const int w    = tid >> 5;
    const int lane = tid & 31;
    const int s    = blockIdx.x * WPB + w;

    float per_seg = 0.0f;

    if (s < n_seg) {
        const int* cu32 = (const int*)cu_raw;
        long long a, bnd;
        if (cu32[1] == 0) {                     // int64 layout (cu[0]=0)
            const long long* cu64 = (const long long*)cu_raw;
            a = cu64[s]; bnd = cu64[s + 1];
        } else {
            a = (long long)cu32[s]; bnd = (long long)cu32[s + 1];
        }
        const int L = (int)(bnd - a);
        const int C = (L + 31) >> 5;
        const float* gx = logits + a;

        // Stage: E+_j in regs (e[]), E-_i in shared (zero-padded); sq, wsum partials.
        float e[4];
        float sq = 0.0f, wsum = 0.0f;
        #pragma unroll
        for (int r = 0; r < 4; ++r) {
            int j = (r << 5) + lane;
            bool valid = (j < L);
            float xv = valid ? gx[j] : 0.0f;
            sq += xv * xv;
            int nv = L - (r << 5); nv = (nv > 32) ? 32 : nv;
            if (valid) wsum += xv * (float)(2 * lane - (nv - 1));
            float xl = xv * LOG2E;
            e[r]     = valid ? ex2f(xl)  : 0.0f;
            em[w][j] = valid ? ex2f(-xl) : 0.0f;
        }
        __syncwarp();

        // Full triangle for this warp's segment: sweeps from each i-chunk against
        // all j-chunks >= i (chain 0 = diagonal).
        float acc = 0.0f, accd = 0.0f;
        const float* base = em[w];
        switch (C) {
            case 1:  sweepN<1>(base, e, acc, accd); break;
            case 2:  sweepN<2>(base,      e,     acc, accd);
                     sweepN<1>(base + 32, e + 1, acc, accd); break;
            case 3:  sweepN<3>(base,      e,     acc, accd);
                     sweepN<2>(base + 32, e + 1, acc, accd);
                     sweepN<1>(base + 64, e + 2, acc, accd); break;
            default: sweepN<4>(base,      e,     acc, accd);
                     sweepN<3>(base + 32, e + 1, acc, accd);
                     sweepN<2>(base + 64, e + 2, acc, accd);
                     sweepN<1>(base + 96, e + 3, acc, accd); break;
        }

        // Fold per-segment uniform coefficients before the warp reduction.
        // tri_nats = LN2*(acc + 0.5*accd) + 0.5*wsum - 0.5*LN2*L
        float invP = 2.0f / ((float)L * (float)(L - 1));
        float v = (acc + 0.5f * accd) * (LN2 * invP)
                + wsum * (0.5f * invP)
                + sq   * (BETA / (float)L);
        #pragma unroll
        for (int o = 16; o > 0; o >>= 1)
            v += __shfl_xor_sync(0xffffffffu, v, o);
        per_seg = v - LN2 / (float)(L - 1);   // constant diag correction
    }

    if (lane == 0) part[w] = per_seg;
    __syncthreads();

    if (tid == 0) {
        float p = 0.0f;
        #pragma unroll
        for (int k = 0; k < WPB; ++k) p += part[k];
        g_part[blockIdx.x] = p;
        __threadfence();
        unsigned d = atomicAdd(&g_done, 1u);
        isLast = (d == gridDim.x - 1);
    }
    __syncthreads();

    if (isLast) {
        float t = 0.0f;
        for (int k = tid; k < (int)gridDim.x; k += TPB) t += g_part[k];  // fixed order
        #pragma unroll
        for (int o = 16; o > 0; o >>= 1) t += __shfl_xor_sync(0xffffffffu, t, o);
        if (lane == 0) ws[w] = t;
        __syncthreads();
        if (w == 0) {
            t = (lane < TPB / 32) ? ws[lane] : 0.0f;
            #pragma unroll
            for (int o = 4; o > 0; o >>= 1) t += __shfl_xor_sync(0xffffffffu, t, o);
            if (lane == 0) {
                out[0] = t / (float)n_seg;
                g_done = 0;   // reset for next graph replay
            }
        }
    }
}

extern "C" void kernel_launch(void* const* d_in, const int* in_sizes, int n_in,
                              void* d_out, int out_size) {
    const float* logits = (const float*)d_in[0];
    const void*  cu     = (const void*)d_in[1];
    int n_seg  = in_sizes[1] - 1;
    int blocks = (n_seg + WPB - 1) / WPB;
    if (blocks > MAXB) blocks = MAXB;

    rm_kernel<<<blocks, TPB>>>(logits, cu, n_seg, (float*)d_out);
}